// round 16
// baseline (speedup 1.0000x reference)
#include <cuda_runtime.h>
#include <cstdint>
#include <math.h>

// Problem dims
#define BATCH 256
#define SEQ   512
#define INDIM 32
#define HID   256
#define G3    768      // 3*HID
#define PREDL 96

// ---------------- scratch (static device memory; no allocation) ----------------
__device__ float g_xp0[(size_t)BATCH * SEQ * G3];   // x @ W_ih_l0^T + b_ih_l0
__device__ float g_xp1[(size_t)BATCH * SEQ * G3];   // h1 @ W_ih_l1^T + b_ih_l1
__device__ float g_h1 [(size_t)BATCH * SEQ * HID];  // layer-0 hidden states
__device__ float g_hfin[BATCH * HID];               // final hidden of layer 1

// ---------------- f32x2 packed helpers ----------------
__device__ __forceinline__ unsigned long long pack2(float lo, float hi) {
    unsigned long long r;
    asm("mov.b64 %0, {%1,%2};" : "=l"(r) : "f"(lo), "f"(hi));
    return r;
}
__device__ __forceinline__ void unpack2(unsigned long long v, float& lo, float& hi) {
    asm("mov.b64 {%0,%1}, %2;" : "=f"(lo), "=f"(hi) : "l"(v));
}
__device__ __forceinline__ unsigned long long ffma2(unsigned long long a,
                                                    unsigned long long b,
                                                    unsigned long long c) {
    unsigned long long d;
    asm("fma.rn.f32x2 %0, %1, %2, %3;" : "=l"(d) : "l"(a), "l"(b), "l"(c));
    return d;
}

__device__ __forceinline__ float fsig(float x) {
    return __fdividef(1.f, 1.f + __expf(-x));
}
__device__ __forceinline__ float ftanh_(float x) {
    return 1.f - __fdividef(2.f, __expf(2.f * x) + 1.f);
}

// =======================================================================
// GEMM v2:  C[M,N] = A[M,K] @ W[N,K]^T + bias[N]   (fp32, FFMA2)
// 128x64 block tile, 8x4 per thread (m-pair FFMA2), 256 threads,
// double-buffered k=16 tiles, one __syncthreads per tile.   (unchanged)
// =======================================================================
__global__ __launch_bounds__(256) void gemm_bias(
        const float* __restrict__ A, const float* __restrict__ W,
        const float* __restrict__ bias, float* __restrict__ C,
        int M, int N, int K) {
    __shared__ float As[2][16][132];
    __shared__ float Bs[2][16][68];
    const int tid = threadIdx.x;
    const int n0 = blockIdx.x * 64;
    const int m0 = blockIdx.y * 128;
    const int tx = tid & 15, ty = tid >> 4;

    const int mA  = tid >> 1;
    const int kcA = (tid & 1) * 2;
    const int nB  = tid >> 2;
    const int kcB = tid & 3;

    const float4* Arow = (const float4*)(A + (size_t)(m0 + mA) * K);
    const float4* Brow = (const float4*)(W + (size_t)(n0 + nB) * K);

    float4 va0 = Arow[kcA];
    float4 va1 = Arow[kcA + 1];
    float4 vb  = Brow[kcB];

    As[0][kcA * 4 + 0][mA] = va0.x; As[0][kcA * 4 + 1][mA] = va0.y;
    As[0][kcA * 4 + 2][mA] = va0.z; As[0][kcA * 4 + 3][mA] = va0.w;
    As[0][kcA * 4 + 4][mA] = va1.x; As[0][kcA * 4 + 5][mA] = va1.y;
    As[0][kcA * 4 + 6][mA] = va1.z; As[0][kcA * 4 + 7][mA] = va1.w;
    Bs[0][kcB * 4 + 0][nB] = vb.x;  Bs[0][kcB * 4 + 1][nB] = vb.y;
    Bs[0][kcB * 4 + 2][nB] = vb.z;  Bs[0][kcB * 4 + 3][nB] = vb.w;
    __syncthreads();

    unsigned long long acc[4][4];
#pragma unroll
    for (int p = 0; p < 4; p++)
#pragma unroll
        for (int n = 0; n < 4; n++) acc[p][n] = 0ull;

    const int ntiles = K >> 4;
    for (int kt = 0; kt < ntiles; kt++) {
        const int s = kt & 1;
        if (kt + 1 < ntiles) {
            va0 = Arow[(kt + 1) * 4 + kcA];
            va1 = Arow[(kt + 1) * 4 + kcA + 1];
            vb  = Brow[(kt + 1) * 4 + kcB];
        }
#pragma unroll
        for (int kk = 0; kk < 16; kk++) {
            const float* ar = &As[s][kk][ty * 8];
            ulonglong2 aA = *(const ulonglong2*)ar;
            ulonglong2 aB = *(const ulonglong2*)(ar + 4);
            float4 b4 = *(const float4*)&Bs[s][kk][tx * 4];
            unsigned long long bp0 = pack2(b4.x, b4.x);
            unsigned long long bp1 = pack2(b4.y, b4.y);
            unsigned long long bp2 = pack2(b4.z, b4.z);
            unsigned long long bp3 = pack2(b4.w, b4.w);
            acc[0][0] = ffma2(aA.x, bp0, acc[0][0]); acc[0][1] = ffma2(aA.x, bp1, acc[0][1]);
            acc[0][2] = ffma2(aA.x, bp2, acc[0][2]); acc[0][3] = ffma2(aA.x, bp3, acc[0][3]);
            acc[1][0] = ffma2(aA.y, bp0, acc[1][0]); acc[1][1] = ffma2(aA.y, bp1, acc[1][1]);
            acc[1][2] = ffma2(aA.y, bp2, acc[1][2]); acc[1][3] = ffma2(aA.y, bp3, acc[1][3]);
            acc[2][0] = ffma2(aB.x, bp0, acc[2][0]); acc[2][1] = ffma2(aB.x, bp1, acc[2][1]);
            acc[2][2] = ffma2(aB.x, bp2, acc[2][2]); acc[2][3] = ffma2(aB.x, bp3, acc[2][3]);
            acc[3][0] = ffma2(aB.y, bp0, acc[3][0]); acc[3][1] = ffma2(aB.y, bp1, acc[3][1]);
            acc[3][2] = ffma2(aB.y, bp2, acc[3][2]); acc[3][3] = ffma2(aB.y, bp3, acc[3][3]);
        }
        if (kt + 1 < ntiles) {
            const int s1 = s ^ 1;
            As[s1][kcA * 4 + 0][mA] = va0.x; As[s1][kcA * 4 + 1][mA] = va0.y;
            As[s1][kcA * 4 + 2][mA] = va0.z; As[s1][kcA * 4 + 3][mA] = va0.w;
            As[s1][kcA * 4 + 4][mA] = va1.x; As[s1][kcA * 4 + 5][mA] = va1.y;
            As[s1][kcA * 4 + 6][mA] = va1.z; As[s1][kcA * 4 + 7][mA] = va1.w;
            Bs[s1][kcB * 4 + 0][nB] = vb.x;  Bs[s1][kcB * 4 + 1][nB] = vb.y;
            Bs[s1][kcB * 4 + 2][nB] = vb.z;  Bs[s1][kcB * 4 + 3][nB] = vb.w;
        }
        __syncthreads();
    }

    float4 bb = *(const float4*)(bias + n0 + tx * 4);
#pragma unroll
    for (int p = 0; p < 4; p++) {
        float l0, h0, l1, h1, l2, h2, l3, h3;
        unpack2(acc[p][0], l0, h0);
        unpack2(acc[p][1], l1, h1);
        unpack2(acc[p][2], l2, h2);
        unpack2(acc[p][3], l3, h3);
        int m = m0 + ty * 8 + p * 2;
        float4 r0 = make_float4(l0 + bb.x, l1 + bb.y, l2 + bb.z, l3 + bb.w);
        float4 r1 = make_float4(h0 + bb.x, h1 + bb.y, h2 + bb.z, h3 + bb.w);
        *(float4*)(C + (size_t)m * N + n0 + tx * 4) = r0;
        *(float4*)(C + (size_t)(m + 1) * N + n0 + tx * 4) = r1;
    }
}

// =======================================================================
// GRU recurrence v8: full-k threads + per-rank pipelined mbarrier waits.
// 256 threads = (u:64) x (bp:4). Thread (u,bp): 2 batches (2bp, 2bp+1),
// 3 gates, ALL 256 k -> complete dot products, ZERO reduce shuffles.
// k swept in rank-rotated order (own rank first); warp waits mbar[src]
// only right before consuming src's 64-k block -> exchange latency hides
// under ~3/4 of the k-loop. No end-of-step barrier.
// mbarriers: 4 src-ranks x 2 stages, count 8 (source CTA's warps);
// WAR safety = v4.1's two-step-separation proof, applied per rank.
// =======================================================================
#define WSTRIDE 260
#define WT_WORDS (192 * WSTRIDE)        // 49920
#define HSTR  292                       // 4 k-blocks x 72 + 4 pad
#define HBUF_WORDS (8 * HSTR)           // 2336 per parity buffer
#define MBAR_OFF_WORDS (WT_WORDS + 2 * HBUF_WORDS)   // 54592
#define GRU_SMEM_FLOATS (MBAR_OFF_WORDS + 16)        // 8 b64 mbarriers
#define GRU_SMEM_BYTES  (GRU_SMEM_FLOATS * 4)        // 218,432 B

__device__ __forceinline__ uint32_t smem_u32(const void* p) {
    return (uint32_t)__cvta_generic_to_shared(p);
}

// acquire-cluster parity wait on a local mbarrier
#define MBAR_WAIT_CLU(mbar, ph) do {                                          \
    uint32_t _m = (mbar), _p = (ph), _d;                                      \
    asm volatile("{\n\t.reg .pred p;\n\t"                                     \
        "mbarrier.try_wait.parity.acquire.cluster.shared::cta.b64 p, [%1], %2, 0x989680;\n\t" \
        "selp.b32 %0, 1, 0, p;\n\t}"                                          \
        : "=r"(_d) : "r"(_m), "r"(_p) : "memory");                            \
    if (!_d) {                                                                \
        asm volatile("{\n\t.reg .pred P1;\n\t"                                \
            "WL_%=:\n\t"                                                      \
            "mbarrier.try_wait.parity.acquire.cluster.shared::cta.b64 P1, [%0], %1, 0x989680;\n\t" \
            "@P1 bra.uni WD_%=;\n\t"                                          \
            "bra.uni WL_%=;\n\t"                                              \
            "WD_%=:\n\t}"                                                     \
            :: "r"(_m), "r"(_p) : "memory");                                  \
    }                                                                         \
} while (0)

template <bool WRITE_ALL>
__global__ __launch_bounds__(256, 1) __cluster_dims__(4, 1, 1)
void gru_layer(const float* __restrict__ xp, const float* __restrict__ W_hh,
               const float* __restrict__ b_hh, float* __restrict__ hout) {
    extern __shared__ float smem[];
    float* Wt   = smem;                 // [192 rows][260]  row = g*64+u
    float* hbuf = smem + WT_WORDS;      // 2 parity x [8 b][292]

    const int tid = threadIdx.x;
    const int bp  = tid & 3;            // batch pair 0..3
    const int u   = tid >> 2;           // 0..63
    uint32_t rank;
    asm("mov.u32 %0, %%cluster_ctarank;" : "=r"(rank));
    const int gu  = (int)rank * 64 + u;
    const int b0  = (blockIdx.x >> 2) * 8;
    const int bA  = 2 * bp, bB = 2 * bp + 1;   // this thread's batches

    const uint32_t mbar_base = smem_u32(smem + MBAR_OFF_WORDS);
    // mbar[r][stage] at r*16 + stage*8

    // Load W_hh slice: Wt[(g*64+u)*260 + k] = W_hh[(g*256 + rank*64 + u)*256 + k]
    for (int idx = tid; idx < 192 * 256; idx += 256) {
        int row = idx >> 8, k = idx & 255;
        int grow = ((row >> 6) << 8) + (int)rank * 64 + (row & 63);
        Wt[row * WSTRIDE + k] = W_hh[grow * 256 + k];
    }
    for (int i = tid; i < 2 * HBUF_WORDS; i += 256) hbuf[i] = 0.f;
    if (tid == 0) {
#pragma unroll
        for (int m = 0; m < 8; m++)
            asm volatile("mbarrier.init.shared.b64 [%0], %1;"
                         :: "r"(mbar_base + m * 8), "r"(8u) : "memory");
    }

    const float bh0 = b_hh[gu], bh1 = b_hh[256 + gu], bh2 = b_hh[512 + gu];

    // xp pointers for the two batches
    const float* pxa = xp + ((size_t)(b0 + bA) * SEQ) * G3 + gu;
    const float* pxb = xp + ((size_t)(b0 + bB) * SEQ) * G3 + gu;

    // h word for (batch b, unit gu) within a parity buffer:
    const int hoffA = bA * HSTR + (int)rank * 72 + u;   // batch bB = +HSTR

    // precompute remote push addresses (2 parities x 4 ranks)
    uint32_t rp0[4], rp1[4];
    {
        uint32_t l0 = smem_u32(hbuf + hoffA);
        uint32_t l1 = smem_u32(hbuf + HBUF_WORDS + hoffA);
#pragma unroll
        for (int p = 0; p < 4; p++) {
            asm("mapa.shared::cluster.u32 %0, %1, %2;" : "=r"(rp0[p]) : "r"(l0), "r"(p));
            asm("mapa.shared::cluster.u32 %0, %1, %2;" : "=r"(rp1[p]) : "r"(l1), "r"(p));
        }
    }
    // precompute remote arrive addresses: mbar[me][stage] in every rank
    uint32_t arr0[4], arr1[4];
    {
        uint32_t m0 = mbar_base + rank * 16;
        uint32_t m1 = m0 + 8;
#pragma unroll
        for (int p = 0; p < 4; p++) {
            asm("mapa.shared::cluster.u32 %0, %1, %2;" : "=r"(arr0[p]) : "r"(m0), "r"(p));
            asm("mapa.shared::cluster.u32 %0, %1, %2;" : "=r"(arr1[p]) : "r"(m1), "r"(p));
        }
    }

    // init (W, hbuf, mbarriers) visible cluster-wide before any push/arrive
    asm volatile("barrier.cluster.arrive.aligned;" ::: "memory");
    asm volatile("barrier.cluster.wait.aligned;" ::: "memory");

    const float* wbR = Wt + u * WSTRIDE;            // gate r row
    const float* wbZ = wbR + 64 * WSTRIDE;          // gate z row
    const float* wbN = wbR + 128 * WSTRIDE;         // gate n row

    for (int t = 0; t < SEQ; t++) {
        const int cur = t & 1, nxt = cur ^ 1;
        const uint32_t wstage = (uint32_t)(((t - 1) & 1) * 8);
        const uint32_t wph    = (uint32_t)(((t - 1) >> 1) & 1);

        // prefetch input projections (consumed in epilogue)
        float xaR = pxa[0], xaZ = pxa[256], xaN = pxa[512];
        float xbR = pxb[0], xbZ = pxb[256], xbN = pxb[512];
        pxa += G3; pxb += G3;

        unsigned long long accRA = 0, accRB = 0, accZA = 0, accZB = 0,
                           accNA = 0, accNB = 0;

        const float* hb  = hbuf + cur * HBUF_WORDS;
        const float* hba = hb + bA * HSTR;
        const float* hbb = hb + bB * HSTR;

#pragma unroll
        for (int i = 0; i < 4; i++) {
            const int src = ((int)rank + i) & 3;
            if (t > 0) MBAR_WAIT_CLU(mbar_base + src * 16 + wstage, wph);
            const float* wR = wbR + src * 64;
            const float* wZ = wbZ + src * 64;
            const float* wN = wbN + src * 64;
            const float* ha = hba + src * 72;
            const float* hx = hbb + src * 72;
#pragma unroll 4
            for (int c = 0; c < 16; c++) {
                const int kl = c * 4;
                ulonglong2 vr = *(const ulonglong2*)(wR + kl);
                ulonglong2 vz = *(const ulonglong2*)(wZ + kl);
                ulonglong2 vn = *(const ulonglong2*)(wN + kl);
                ulonglong2 h0 = *(const ulonglong2*)(ha + kl);
                ulonglong2 h1 = *(const ulonglong2*)(hx + kl);
                accRA = ffma2(vr.x, h0.x, accRA); accRA = ffma2(vr.y, h0.y, accRA);
                accRB = ffma2(vr.x, h1.x, accRB); accRB = ffma2(vr.y, h1.y, accRB);
                accZA = ffma2(vz.x, h0.x, accZA); accZA = ffma2(vz.y, h0.y, accZA);
                accZB = ffma2(vz.x, h1.x, accZB); accZB = ffma2(vz.y, h1.y, accZB);
                accNA = ffma2(vn.x, h0.x, accNA); accNA = ffma2(vn.y, h0.y, accNA);
                accNB = ffma2(vn.x, h1.x, accNB); accNB = ffma2(vn.y, h1.y, accNB);
            }
        }

        // previous h for the two batches
        float hpA = hb[hoffA];
        float hpB = hb[hoffA + HSTR];

        // finalize dot products (no shuffles needed)
        float lo, hi;
        unpack2(accRA, lo, hi); float sRA = lo + hi;
        unpack2(accRB, lo, hi); float sRB = lo + hi;
        unpack2(accZA, lo, hi); float sZA = lo + hi;
        unpack2(accZB, lo, hi); float sZB = lo + hi;
        unpack2(accNA, lo, hi); float sNA = lo + hi;
        unpack2(accNB, lo, hi); float sNB = lo + hi;

        float rA = fsig(xaR + sRA + bh0);
        float zA = fsig(xaZ + sZA + bh1);
        float nA = ftanh_(xaN + rA * (sNA + bh2));
        float hnA = (1.f - zA) * nA + zA * hpA;

        float rB = fsig(xbR + sRB + bh0);
        float zB = fsig(xbZ + sZB + bh1);
        float nB = ftanh_(xbN + rB * (sNB + bh2));
        float hnB = (1.f - zB) * nB + zB * hpB;

        // push both batches to all 4 CTAs' next buffer
#pragma unroll
        for (int p = 0; p < 4; p++) {
            uint32_t ra = nxt ? rp1[p] : rp0[p];
            asm volatile("st.shared::cluster.f32 [%0], %1;"
                         :: "r"(ra), "f"(hnA) : "memory");
            asm volatile("st.shared::cluster.f32 [%0+1168], %1;"   // +HSTR*4 B
                         :: "r"(ra), "f"(hnB) : "memory");
        }

        // warp-elected release-arrive on mbar[me][t&1] of every CTA
        __syncwarp();
        if ((tid & 31) == 0) {
#pragma unroll
            for (int p = 0; p < 4; p++) {
                uint32_t ra = (t & 1) ? arr1[p] : arr0[p];
                asm volatile("mbarrier.arrive.release.cluster.shared::cluster.b64 _, [%0];"
                             :: "r"(ra) : "memory");
            }
        }

        // global h writes (no end-of-step barrier; next step's waits gate us)
        if (WRITE_ALL) {
            hout[((size_t)(b0 + bA) * SEQ + t) * HID + gu] = hnA;
            hout[((size_t)(b0 + bB) * SEQ + t) * HID + gu] = hnB;
        } else if (t == SEQ - 1) {
            hout[(b0 + bA) * HID + gu] = hnA;
            hout[(b0 + bB) * HID + gu] = hnB;
        }
    }

    // Drain in-flight remote stores/arrives before any CTA's SMEM is freed.
    asm volatile("barrier.cluster.arrive.aligned;" ::: "memory");
    asm volatile("barrier.cluster.wait.aligned;" ::: "memory");
}

// =======================================================================
// Final projection + 96-step linear state-space decode. 1 block per batch row.
// =======================================================================
__global__ void final_kernel(const float* __restrict__ hfin, const float* __restrict__ Wp,
                             const float* __restrict__ bp, const float* __restrict__ Cm,
                             const float* __restrict__ rld, const float* __restrict__ rtd,
                             const float* __restrict__ rg, const float* __restrict__ om,
                             float* __restrict__ out) {
    __shared__ float hs[256];
    __shared__ float ss[128];
    const int b = blockIdx.x, tid = threadIdx.x;  // 128 threads
    hs[tid]       = hfin[b * 256 + tid];
    hs[tid + 128] = hfin[b * 256 + 128 + tid];
    __syncthreads();

    float acc = bp[tid];
    const float* w = Wp + tid * 256;
#pragma unroll 8
    for (int k = 0; k < 256; k++) acc += w[k] * hs[k];
    ss[tid] = acc;
    __syncthreads();

    if (tid < 32) {
        const int d = tid;
        float s0 = ss[d * 4 + 0], s1 = ss[d * 4 + 1], s2 = ss[d * 4 + 2], s3 = ss[d * 4 + 3];
        const float al = 1.f / (1.f + expf(-rld[d])) * 0.15f + 0.85f;
        const float at = 1.f / (1.f + expf(-rtd[d])) * 0.25f + 0.70f;
        const float g  = 1.f / (1.f + expf(-rg[d]))  * 0.20f + 0.80f;
        const float c = cosf(om[d]), sn = sinf(om[d]);
        const float r00 = g * c, r01 = -g * sn, r10 = g * sn, r11 = g * c;
        const float C0 = Cm[d * 4 + 0], C1 = Cm[d * 4 + 1];
        const float C2 = Cm[d * 4 + 2], C3 = Cm[d * 4 + 3];
        float* ob = out + (size_t)b * PREDL * 32 + d;
#pragma unroll 4
        for (int t = 0; t < PREDL; t++) {
            float n0 = s0 * al;
            float n1 = s1 * at;
            float n2 = s2 * r00 + s3 * r10;
            float n3 = s2 * r01 + s3 * r11;
            ob[t * 32] = C0 * n0 + C1 * n1 + C2 * n2 + C3 * n3;
            s0 = n0; s1 = n1; s2 = n2; s3 = n3;
        }
    }
}

// =======================================================================
extern "C" void kernel_launch(void* const* d_in, const int* in_sizes, int n_in,
                              void* d_out, int out_size) {
    const float* x     = (const float*)d_in[0];
    const float* Wih0  = (const float*)d_in[1];
    const float* Whh0  = (const float*)d_in[2];
    const float* bih0  = (const float*)d_in[3];
    const float* bhh0  = (const float*)d_in[4];
    const float* Wih1  = (const float*)d_in[5];
    const float* Whh1  = (const float*)d_in[6];
    const float* bih1  = (const float*)d_in[7];
    const float* bhh1  = (const float*)d_in[8];
    const float* Wproj = (const float*)d_in[9];
    const float* bproj = (const float*)d_in[10];
    const float* Cm    = (const float*)d_in[11];
    const float* rld   = (const float*)d_in[12];
    const float* rtd   = (const float*)d_in[13];
    const float* rg    = (const float*)d_in[14];
    const float* om    = (const float*)d_in[15];
    float* out = (float*)d_out;

    float *xp0, *xp1, *h1, *hfin;
    cudaGetSymbolAddress((void**)&xp0,  g_xp0);
    cudaGetSymbolAddress((void**)&xp1,  g_xp1);
    cudaGetSymbolAddress((void**)&h1,   g_h1);
    cudaGetSymbolAddress((void**)&hfin, g_hfin);

    cudaFuncSetAttribute(gru_layer<true>,  cudaFuncAttributeMaxDynamicSharedMemorySize, GRU_SMEM_BYTES);
    cudaFuncSetAttribute(gru_layer<false>, cudaFuncAttributeMaxDynamicSharedMemorySize, GRU_SMEM_BYTES);

    const int M = BATCH * SEQ;  // 131072
    dim3 ggrid(G3 / 64, M / 128);

    // Phase 1: layer-0 input projection (K=32)
    gemm_bias<<<ggrid, 256>>>(x, Wih0, bih0, xp0, M, G3, INDIM);
    // Phase 2: layer-0 recurrence, write all h1
    gru_layer<true><<<128, 256, GRU_SMEM_BYTES>>>(xp0, Whh0, bhh0, h1);
    // Phase 3: layer-1 input projection (K=256)
    gemm_bias<<<ggrid, 256>>>(h1, Wih1, bih1, xp1, M, G3, HID);
    // Phase 4: layer-1 recurrence, final h only
    gru_layer<false><<<128, 256, GRU_SMEM_BYTES>>>(xp1, Whh1, bhh1, hfin);
    // Phase 5: projection + decode scan
    final_kernel<<<256, 128>>>(hfin, Wproj, bproj, Cm, rld, rtd, rg, om, out);
}

// round 17
// speedup vs baseline: 1.0004x; 1.0004x over previous
#include <cuda_runtime.h>
#include <cstdint>
#include <math.h>

// Problem dims
#define BATCH 256
#define SEQ   512
#define INDIM 32
#define HID   256
#define G3    768      // 3*HID
#define PREDL 96

// ---------------- scratch (static device memory; no allocation) ----------------
__device__ float g_xp0[(size_t)BATCH * SEQ * G3];   // x @ W_ih_l0^T + b_ih_l0
__device__ float g_xp1[(size_t)BATCH * SEQ * G3];   // h1 @ W_ih_l1^T + b_ih_l1
__device__ float g_h1 [(size_t)BATCH * SEQ * HID];  // layer-0 hidden states
__device__ float g_hfin[BATCH * HID];               // final hidden of layer 1

// ---------------- f32x2 packed helpers ----------------
__device__ __forceinline__ unsigned long long pack2(float lo, float hi) {
    unsigned long long r;
    asm("mov.b64 %0, {%1,%2};" : "=l"(r) : "f"(lo), "f"(hi));
    return r;
}
__device__ __forceinline__ void unpack2(unsigned long long v, float& lo, float& hi) {
    asm("mov.b64 {%0,%1}, %2;" : "=f"(lo), "=f"(hi) : "l"(v));
}
__device__ __forceinline__ unsigned long long ffma2(unsigned long long a,
                                                    unsigned long long b,
                                                    unsigned long long c) {
    unsigned long long d;
    asm("fma.rn.f32x2 %0, %1, %2, %3;" : "=l"(d) : "l"(a), "l"(b), "l"(c));
    return d;
}

__device__ __forceinline__ float fsig(float x) {
    return __fdividef(1.f, 1.f + __expf(-x));
}
__device__ __forceinline__ float ftanh_(float x) {
    return 1.f - __fdividef(2.f, __expf(2.f * x) + 1.f);
}

// =======================================================================
// GEMM v2:  C[M,N] = A[M,K] @ W[N,K]^T + bias[N]   (fp32, FFMA2)
// 128x64 block tile, 8x4 per thread (m-pair FFMA2), 256 threads,
// double-buffered k=16 tiles, one __syncthreads per tile.   (unchanged)
// =======================================================================
__global__ __launch_bounds__(256) void gemm_bias(
        const float* __restrict__ A, const float* __restrict__ W,
        const float* __restrict__ bias, float* __restrict__ C,
        int M, int N, int K) {
    __shared__ float As[2][16][132];
    __shared__ float Bs[2][16][68];
    const int tid = threadIdx.x;
    const int n0 = blockIdx.x * 64;
    const int m0 = blockIdx.y * 128;
    const int tx = tid & 15, ty = tid >> 4;

    const int mA  = tid >> 1;
    const int kcA = (tid & 1) * 2;
    const int nB  = tid >> 2;
    const int kcB = tid & 3;

    const float4* Arow = (const float4*)(A + (size_t)(m0 + mA) * K);
    const float4* Brow = (const float4*)(W + (size_t)(n0 + nB) * K);

    float4 va0 = Arow[kcA];
    float4 va1 = Arow[kcA + 1];
    float4 vb  = Brow[kcB];

    As[0][kcA * 4 + 0][mA] = va0.x; As[0][kcA * 4 + 1][mA] = va0.y;
    As[0][kcA * 4 + 2][mA] = va0.z; As[0][kcA * 4 + 3][mA] = va0.w;
    As[0][kcA * 4 + 4][mA] = va1.x; As[0][kcA * 4 + 5][mA] = va1.y;
    As[0][kcA * 4 + 6][mA] = va1.z; As[0][kcA * 4 + 7][mA] = va1.w;
    Bs[0][kcB * 4 + 0][nB] = vb.x;  Bs[0][kcB * 4 + 1][nB] = vb.y;
    Bs[0][kcB * 4 + 2][nB] = vb.z;  Bs[0][kcB * 4 + 3][nB] = vb.w;
    __syncthreads();

    unsigned long long acc[4][4];
#pragma unroll
    for (int p = 0; p < 4; p++)
#pragma unroll
        for (int n = 0; n < 4; n++) acc[p][n] = 0ull;

    const int ntiles = K >> 4;
    for (int kt = 0; kt < ntiles; kt++) {
        const int s = kt & 1;
        if (kt + 1 < ntiles) {
            va0 = Arow[(kt + 1) * 4 + kcA];
            va1 = Arow[(kt + 1) * 4 + kcA + 1];
            vb  = Brow[(kt + 1) * 4 + kcB];
        }
#pragma unroll
        for (int kk = 0; kk < 16; kk++) {
            const float* ar = &As[s][kk][ty * 8];
            ulonglong2 aA = *(const ulonglong2*)ar;
            ulonglong2 aB = *(const ulonglong2*)(ar + 4);
            float4 b4 = *(const float4*)&Bs[s][kk][tx * 4];
            unsigned long long bp0 = pack2(b4.x, b4.x);
            unsigned long long bp1 = pack2(b4.y, b4.y);
            unsigned long long bp2 = pack2(b4.z, b4.z);
            unsigned long long bp3 = pack2(b4.w, b4.w);
            acc[0][0] = ffma2(aA.x, bp0, acc[0][0]); acc[0][1] = ffma2(aA.x, bp1, acc[0][1]);
            acc[0][2] = ffma2(aA.x, bp2, acc[0][2]); acc[0][3] = ffma2(aA.x, bp3, acc[0][3]);
            acc[1][0] = ffma2(aA.y, bp0, acc[1][0]); acc[1][1] = ffma2(aA.y, bp1, acc[1][1]);
            acc[1][2] = ffma2(aA.y, bp2, acc[1][2]); acc[1][3] = ffma2(aA.y, bp3, acc[1][3]);
            acc[2][0] = ffma2(aB.x, bp0, acc[2][0]); acc[2][1] = ffma2(aB.x, bp1, acc[2][1]);
            acc[2][2] = ffma2(aB.x, bp2, acc[2][2]); acc[2][3] = ffma2(aB.x, bp3, acc[2][3]);
            acc[3][0] = ffma2(aB.y, bp0, acc[3][0]); acc[3][1] = ffma2(aB.y, bp1, acc[3][1]);
            acc[3][2] = ffma2(aB.y, bp2, acc[3][2]); acc[3][3] = ffma2(aB.y, bp3, acc[3][3]);
        }
        if (kt + 1 < ntiles) {
            const int s1 = s ^ 1;
            As[s1][kcA * 4 + 0][mA] = va0.x; As[s1][kcA * 4 + 1][mA] = va0.y;
            As[s1][kcA * 4 + 2][mA] = va0.z; As[s1][kcA * 4 + 3][mA] = va0.w;
            As[s1][kcA * 4 + 4][mA] = va1.x; As[s1][kcA * 4 + 5][mA] = va1.y;
            As[s1][kcA * 4 + 6][mA] = va1.z; As[s1][kcA * 4 + 7][mA] = va1.w;
            Bs[s1][kcB * 4 + 0][nB] = vb.x;  Bs[s1][kcB * 4 + 1][nB] = vb.y;
            Bs[s1][kcB * 4 + 2][nB] = vb.z;  Bs[s1][kcB * 4 + 3][nB] = vb.w;
        }
        __syncthreads();
    }

    float4 bb = *(const float4*)(bias + n0 + tx * 4);
#pragma unroll
    for (int p = 0; p < 4; p++) {
        float l0, h0, l1, h1, l2, h2, l3, h3;
        unpack2(acc[p][0], l0, h0);
        unpack2(acc[p][1], l1, h1);
        unpack2(acc[p][2], l2, h2);
        unpack2(acc[p][3], l3, h3);
        int m = m0 + ty * 8 + p * 2;
        float4 r0 = make_float4(l0 + bb.x, l1 + bb.y, l2 + bb.z, l3 + bb.w);
        float4 r1 = make_float4(h0 + bb.x, h1 + bb.y, h2 + bb.z, h3 + bb.w);
        *(float4*)(C + (size_t)m * N + n0 + tx * 4) = r0;
        *(float4*)(C + (size_t)(m + 1) * N + n0 + tx * 4) = r1;
    }
}

// =======================================================================
// GRU recurrence v8: full-k threads + per-rank pipelined mbarrier waits.
// 256 threads = (u:64) x (bp:4). Thread (u,bp): 2 batches (2bp, 2bp+1),
// 3 gates, ALL 256 k -> complete dot products, ZERO reduce shuffles.
// k swept in rank-rotated order (own rank first); warp waits mbar[src]
// only right before consuming src's 64-k block -> exchange latency hides
// under ~3/4 of the k-loop. No end-of-step barrier.
// mbarriers: 4 src-ranks x 2 stages, count 8 (source CTA's warps);
// WAR safety = v4.1's two-step-separation proof, applied per rank.
// =======================================================================
#define WSTRIDE 260
#define WT_WORDS (192 * WSTRIDE)        // 49920
#define HSTR  292                       // 4 k-blocks x 72 + 4 pad
#define HBUF_WORDS (8 * HSTR)           // 2336 per parity buffer
#define MBAR_OFF_WORDS (WT_WORDS + 2 * HBUF_WORDS)   // 54592
#define GRU_SMEM_FLOATS (MBAR_OFF_WORDS + 16)        // 8 b64 mbarriers
#define GRU_SMEM_BYTES  (GRU_SMEM_FLOATS * 4)        // 218,432 B

__device__ __forceinline__ uint32_t smem_u32(const void* p) {
    return (uint32_t)__cvta_generic_to_shared(p);
}

// acquire-cluster parity wait on a local mbarrier
#define MBAR_WAIT_CLU(mbar, ph) do {                                          \
    uint32_t _m = (mbar), _p = (ph), _d;                                      \
    asm volatile("{\n\t.reg .pred p;\n\t"                                     \
        "mbarrier.try_wait.parity.acquire.cluster.shared::cta.b64 p, [%1], %2, 0x989680;\n\t" \
        "selp.b32 %0, 1, 0, p;\n\t}"                                          \
        : "=r"(_d) : "r"(_m), "r"(_p) : "memory");                            \
    if (!_d) {                                                                \
        asm volatile("{\n\t.reg .pred P1;\n\t"                                \
            "WL_%=:\n\t"                                                      \
            "mbarrier.try_wait.parity.acquire.cluster.shared::cta.b64 P1, [%0], %1, 0x989680;\n\t" \
            "@P1 bra.uni WD_%=;\n\t"                                          \
            "bra.uni WL_%=;\n\t"                                              \
            "WD_%=:\n\t}"                                                     \
            :: "r"(_m), "r"(_p) : "memory");                                  \
    }                                                                         \
} while (0)

template <bool WRITE_ALL>
__global__ __launch_bounds__(256, 1) __cluster_dims__(4, 1, 1)
void gru_layer(const float* __restrict__ xp, const float* __restrict__ W_hh,
               const float* __restrict__ b_hh, float* __restrict__ hout) {
    extern __shared__ float smem[];
    float* Wt   = smem;                 // [192 rows][260]  row = g*64+u
    float* hbuf = smem + WT_WORDS;      // 2 parity x [8 b][292]

    const int tid = threadIdx.x;
    const int bp  = tid & 3;            // batch pair 0..3
    const int u   = tid >> 2;           // 0..63
    uint32_t rank;
    asm("mov.u32 %0, %%cluster_ctarank;" : "=r"(rank));
    const int gu  = (int)rank * 64 + u;
    const int b0  = (blockIdx.x >> 2) * 8;
    const int bA  = 2 * bp, bB = 2 * bp + 1;   // this thread's batches

    const uint32_t mbar_base = smem_u32(smem + MBAR_OFF_WORDS);
    // mbar[r][stage] at r*16 + stage*8

    // Load W_hh slice: Wt[(g*64+u)*260 + k] = W_hh[(g*256 + rank*64 + u)*256 + k]
    for (int idx = tid; idx < 192 * 256; idx += 256) {
        int row = idx >> 8, k = idx & 255;
        int grow = ((row >> 6) << 8) + (int)rank * 64 + (row & 63);
        Wt[row * WSTRIDE + k] = W_hh[grow * 256 + k];
    }
    for (int i = tid; i < 2 * HBUF_WORDS; i += 256) hbuf[i] = 0.f;
    if (tid == 0) {
#pragma unroll
        for (int m = 0; m < 8; m++)
            asm volatile("mbarrier.init.shared.b64 [%0], %1;"
                         :: "r"(mbar_base + m * 8), "r"(8u) : "memory");
    }

    const float bh0 = b_hh[gu], bh1 = b_hh[256 + gu], bh2 = b_hh[512 + gu];

    // xp pointers for the two batches
    const float* pxa = xp + ((size_t)(b0 + bA) * SEQ) * G3 + gu;
    const float* pxb = xp + ((size_t)(b0 + bB) * SEQ) * G3 + gu;

    // h word for (batch b, unit gu) within a parity buffer:
    const int hoffA = bA * HSTR + (int)rank * 72 + u;   // batch bB = +HSTR

    // precompute remote push addresses (2 parities x 4 ranks)
    uint32_t rp0[4], rp1[4];
    {
        uint32_t l0 = smem_u32(hbuf + hoffA);
        uint32_t l1 = smem_u32(hbuf + HBUF_WORDS + hoffA);
#pragma unroll
        for (int p = 0; p < 4; p++) {
            asm("mapa.shared::cluster.u32 %0, %1, %2;" : "=r"(rp0[p]) : "r"(l0), "r"(p));
            asm("mapa.shared::cluster.u32 %0, %1, %2;" : "=r"(rp1[p]) : "r"(l1), "r"(p));
        }
    }
    // precompute remote arrive addresses: mbar[me][stage] in every rank
    uint32_t arr0[4], arr1[4];
    {
        uint32_t m0 = mbar_base + rank * 16;
        uint32_t m1 = m0 + 8;
#pragma unroll
        for (int p = 0; p < 4; p++) {
            asm("mapa.shared::cluster.u32 %0, %1, %2;" : "=r"(arr0[p]) : "r"(m0), "r"(p));
            asm("mapa.shared::cluster.u32 %0, %1, %2;" : "=r"(arr1[p]) : "r"(m1), "r"(p));
        }
    }

    // init (W, hbuf, mbarriers) visible cluster-wide before any push/arrive
    asm volatile("barrier.cluster.arrive.aligned;" ::: "memory");
    asm volatile("barrier.cluster.wait.aligned;" ::: "memory");

    const float* wbR = Wt + u * WSTRIDE;            // gate r row
    const float* wbZ = wbR + 64 * WSTRIDE;          // gate z row
    const float* wbN = wbR + 128 * WSTRIDE;         // gate n row

    for (int t = 0; t < SEQ; t++) {
        const int cur = t & 1, nxt = cur ^ 1;
        const uint32_t wstage = (uint32_t)(((t - 1) & 1) * 8);
        const uint32_t wph    = (uint32_t)(((t - 1) >> 1) & 1);

        // prefetch input projections (consumed in epilogue)
        float xaR = pxa[0], xaZ = pxa[256], xaN = pxa[512];
        float xbR = pxb[0], xbZ = pxb[256], xbN = pxb[512];
        pxa += G3; pxb += G3;

        unsigned long long accRA = 0, accRB = 0, accZA = 0, accZB = 0,
                           accNA = 0, accNB = 0;

        const float* hb  = hbuf + cur * HBUF_WORDS;
        const float* hba = hb + bA * HSTR;
        const float* hbb = hb + bB * HSTR;

#pragma unroll
        for (int i = 0; i < 4; i++) {
            const int src = ((int)rank + i) & 3;
            if (t > 0) MBAR_WAIT_CLU(mbar_base + src * 16 + wstage, wph);
            const float* wR = wbR + src * 64;
            const float* wZ = wbZ + src * 64;
            const float* wN = wbN + src * 64;
            const float* ha = hba + src * 72;
            const float* hx = hbb + src * 72;
#pragma unroll 4
            for (int c = 0; c < 16; c++) {
                const int kl = c * 4;
                ulonglong2 vr = *(const ulonglong2*)(wR + kl);
                ulonglong2 vz = *(const ulonglong2*)(wZ + kl);
                ulonglong2 vn = *(const ulonglong2*)(wN + kl);
                ulonglong2 h0 = *(const ulonglong2*)(ha + kl);
                ulonglong2 h1 = *(const ulonglong2*)(hx + kl);
                accRA = ffma2(vr.x, h0.x, accRA); accRA = ffma2(vr.y, h0.y, accRA);
                accRB = ffma2(vr.x, h1.x, accRB); accRB = ffma2(vr.y, h1.y, accRB);
                accZA = ffma2(vz.x, h0.x, accZA); accZA = ffma2(vz.y, h0.y, accZA);
                accZB = ffma2(vz.x, h1.x, accZB); accZB = ffma2(vz.y, h1.y, accZB);
                accNA = ffma2(vn.x, h0.x, accNA); accNA = ffma2(vn.y, h0.y, accNA);
                accNB = ffma2(vn.x, h1.x, accNB); accNB = ffma2(vn.y, h1.y, accNB);
            }
        }

        // previous h for the two batches
        float hpA = hb[hoffA];
        float hpB = hb[hoffA + HSTR];

        // finalize dot products (no shuffles needed)
        float lo, hi;
        unpack2(accRA, lo, hi); float sRA = lo + hi;
        unpack2(accRB, lo, hi); float sRB = lo + hi;
        unpack2(accZA, lo, hi); float sZA = lo + hi;
        unpack2(accZB, lo, hi); float sZB = lo + hi;
        unpack2(accNA, lo, hi); float sNA = lo + hi;
        unpack2(accNB, lo, hi); float sNB = lo + hi;

        float rA = fsig(xaR + sRA + bh0);
        float zA = fsig(xaZ + sZA + bh1);
        float nA = ftanh_(xaN + rA * (sNA + bh2));
        float hnA = (1.f - zA) * nA + zA * hpA;

        float rB = fsig(xbR + sRB + bh0);
        float zB = fsig(xbZ + sZB + bh1);
        float nB = ftanh_(xbN + rB * (sNB + bh2));
        float hnB = (1.f - zB) * nB + zB * hpB;

        // push both batches to all 4 CTAs' next buffer
#pragma unroll
        for (int p = 0; p < 4; p++) {
            uint32_t ra = nxt ? rp1[p] : rp0[p];
            asm volatile("st.shared::cluster.f32 [%0], %1;"
                         :: "r"(ra), "f"(hnA) : "memory");
            asm volatile("st.shared::cluster.f32 [%0+1168], %1;"   // +HSTR*4 B
                         :: "r"(ra), "f"(hnB) : "memory");
        }

        // warp-elected release-arrive on mbar[me][t&1] of every CTA
        __syncwarp();
        if ((tid & 31) == 0) {
#pragma unroll
            for (int p = 0; p < 4; p++) {
                uint32_t ra = (t & 1) ? arr1[p] : arr0[p];
                asm volatile("mbarrier.arrive.release.cluster.shared::cluster.b64 _, [%0];"
                             :: "r"(ra) : "memory");
            }
        }

        // global h writes (no end-of-step barrier; next step's waits gate us)
        if (WRITE_ALL) {
            hout[((size_t)(b0 + bA) * SEQ + t) * HID + gu] = hnA;
            hout[((size_t)(b0 + bB) * SEQ + t) * HID + gu] = hnB;
        } else if (t == SEQ - 1) {
            hout[(b0 + bA) * HID + gu] = hnA;
            hout[(b0 + bB) * HID + gu] = hnB;
        }
    }

    // Drain in-flight remote stores/arrives before any CTA's SMEM is freed.
    asm volatile("barrier.cluster.arrive.aligned;" ::: "memory");
    asm volatile("barrier.cluster.wait.aligned;" ::: "memory");
}

// =======================================================================
// Final projection + 96-step linear state-space decode. 1 block per batch row.
// =======================================================================
__global__ void final_kernel(const float* __restrict__ hfin, const float* __restrict__ Wp,
                             const float* __restrict__ bp, const float* __restrict__ Cm,
                             const float* __restrict__ rld, const float* __restrict__ rtd,
                             const float* __restrict__ rg, const float* __restrict__ om,
                             float* __restrict__ out) {
    __shared__ float hs[256];
    __shared__ float ss[128];
    const int b = blockIdx.x, tid = threadIdx.x;  // 128 threads
    hs[tid]       = hfin[b * 256 + tid];
    hs[tid + 128] = hfin[b * 256 + 128 + tid];
    __syncthreads();

    float acc = bp[tid];
    const float* w = Wp + tid * 256;
#pragma unroll 8
    for (int k = 0; k < 256; k++) acc += w[k] * hs[k];
    ss[tid] = acc;
    __syncthreads();

    if (tid < 32) {
        const int d = tid;
        float s0 = ss[d * 4 + 0], s1 = ss[d * 4 + 1], s2 = ss[d * 4 + 2], s3 = ss[d * 4 + 3];
        const float al = 1.f / (1.f + expf(-rld[d])) * 0.15f + 0.85f;
        const float at = 1.f / (1.f + expf(-rtd[d])) * 0.25f + 0.70f;
        const float g  = 1.f / (1.f + expf(-rg[d]))  * 0.20f + 0.80f;
        const float c = cosf(om[d]), sn = sinf(om[d]);
        const float r00 = g * c, r01 = -g * sn, r10 = g * sn, r11 = g * c;
        const float C0 = Cm[d * 4 + 0], C1 = Cm[d * 4 + 1];
        const float C2 = Cm[d * 4 + 2], C3 = Cm[d * 4 + 3];
        float* ob = out + (size_t)b * PREDL * 32 + d;
#pragma unroll 4
        for (int t = 0; t < PREDL; t++) {
            float n0 = s0 * al;
            float n1 = s1 * at;
            float n2 = s2 * r00 + s3 * r10;
            float n3 = s2 * r01 + s3 * r11;
            ob[t * 32] = C0 * n0 + C1 * n1 + C2 * n2 + C3 * n3;
            s0 = n0; s1 = n1; s2 = n2; s3 = n3;
        }
    }
}

// =======================================================================
extern "C" void kernel_launch(void* const* d_in, const int* in_sizes, int n_in,
                              void* d_out, int out_size) {
    const float* x     = (const float*)d_in[0];
    const float* Wih0  = (const float*)d_in[1];
    const float* Whh0  = (const float*)d_in[2];
    const float* bih0  = (const float*)d_in[3];
    const float* bhh0  = (const float*)d_in[4];
    const float* Wih1  = (const float*)d_in[5];
    const float* Whh1  = (const float*)d_in[6];
    const float* bih1  = (const float*)d_in[7];
    const float* bhh1  = (const float*)d_in[8];
    const float* Wproj = (const float*)d_in[9];
    const float* bproj = (const float*)d_in[10];
    const float* Cm    = (const float*)d_in[11];
    const float* rld   = (const float*)d_in[12];
    const float* rtd   = (const float*)d_in[13];
    const float* rg    = (const float*)d_in[14];
    const float* om    = (const float*)d_in[15];
    float* out = (float*)d_out;

    float *xp0, *xp1, *h1, *hfin;
    cudaGetSymbolAddress((void**)&xp0,  g_xp0);
    cudaGetSymbolAddress((void**)&xp1,  g_xp1);
    cudaGetSymbolAddress((void**)&h1,   g_h1);
    cudaGetSymbolAddress((void**)&hfin, g_hfin);

    cudaFuncSetAttribute(gru_layer<true>,  cudaFuncAttributeMaxDynamicSharedMemorySize, GRU_SMEM_BYTES);
    cudaFuncSetAttribute(gru_layer<false>, cudaFuncAttributeMaxDynamicSharedMemorySize, GRU_SMEM_BYTES);

    const int M = BATCH * SEQ;  // 131072
    dim3 ggrid(G3 / 64, M / 128);

    // Phase 1: layer-0 input projection (K=32)
    gemm_bias<<<ggrid, 256>>>(x, Wih0, bih0, xp0, M, G3, INDIM);
    // Phase 2: layer-0 recurrence, write all h1
    gru_layer<true><<<128, 256, GRU_SMEM_BYTES>>>(xp0, Whh0, bhh0, h1);
    // Phase 3: layer-1 input projection (K=256)
    gemm_bias<<<ggrid, 256>>>(h1, Wih1, bih1, xp1, M, G3, HID);
    // Phase 4: layer-1 recurrence, final h only
    gru_layer<false><<<128, 256, GRU_SMEM_BYTES>>>(xp1, Whh1, bhh1, hfin);
    // Phase 5: projection + decode scan
    final_kernel<<<256, 128>>>(hfin, Wproj, bproj, Cm, rld, rtd, rg, om, out);
}